// round 8
// baseline (speedup 1.0000x reference)
#include <cuda_runtime.h>
#include <cuda_fp16.h>
#include <math.h>
#include <stdint.h>

#define NN 50000
#define EE 800000
#define DIN 128
#define DH 64
#define DOUT 16
#define NCHUNK ((NN + 255) / 256)   // 196
#define EBLK ((EE + 255) / 256)     // 3125

// Scratch (device globals; no allocation allowed)
__device__ __align__(256) __half g_th[NN * DH];      // ping
__device__ __align__(256) __half g_ha[NN * DH];      // pong
__device__ float g_dinv[NN];
__device__ int g_cnt[NN];
__device__ int g_lexcl[NN];
__device__ int g_rowptr[NN + 1];
__device__ int g_loc[EE];
__device__ int g_col[EE];
__device__ int g_chtot[256];

// ---------------------------------------------------------------- preprocessing
__global__ void k_count(const int* __restrict__ dst) {
    int i = blockIdx.x * blockDim.x + threadIdx.x;
    if (i < EE) g_loc[i] = atomicAdd(&g_cnt[dst[i]], 1);
}

__global__ void k_scan1() {
    __shared__ int wsum[8];
    int tid = threadIdx.x;
    int i = blockIdx.x * 256 + tid;
    int v = (i < NN) ? g_cnt[i] : 0;
    if (i < NN) g_dinv[i] = rsqrtf((float)(v + 1));
    int lane = tid & 31, w = tid >> 5;
    int incl = v;
#pragma unroll
    for (int o = 1; o < 32; o <<= 1) {
        int t = __shfl_up_sync(0xffffffffu, incl, o);
        if (lane >= o) incl += t;
    }
    if (lane == 31) wsum[w] = incl;
    __syncthreads();
    if (w == 0) {
        int s = (lane < 8) ? wsum[lane] : 0;
#pragma unroll
        for (int o = 1; o < 8; o <<= 1) {
            int t = __shfl_up_sync(0xffffffffu, s, o);
            if (lane >= o) s += t;
        }
        if (lane < 8) wsum[lane] = s;
    }
    __syncthreads();
    int woff = (w > 0) ? wsum[w - 1] : 0;
    if (i < NN) g_lexcl[i] = woff + incl - v;
    if (tid == 255) g_chtot[blockIdx.x] = woff + incl;
}

__global__ void k_finish(const int* __restrict__ src, const int* __restrict__ dst) {
    __shared__ int soff[256];
    __shared__ int wsum[8];
    int tid = threadIdx.x;
    {
        int v = (tid < NCHUNK) ? g_chtot[tid] : 0;
        int lane = tid & 31, w = tid >> 5;
        int incl = v;
#pragma unroll
        for (int o = 1; o < 32; o <<= 1) {
            int t = __shfl_up_sync(0xffffffffu, incl, o);
            if (lane >= o) incl += t;
        }
        if (lane == 31) wsum[w] = incl;
        __syncthreads();
        if (w == 0) {
            int s = (lane < 8) ? wsum[lane] : 0;
#pragma unroll
            for (int o = 1; o < 8; o <<= 1) {
                int t = __shfl_up_sync(0xffffffffu, s, o);
                if (lane >= o) s += t;
            }
            if (lane < 8) wsum[lane] = s;
        }
        __syncthreads();
        int woff = (w > 0) ? wsum[w - 1] : 0;
        soff[tid] = woff + incl - v;
        __syncthreads();
    }
    int b = blockIdx.x;
    if (b < NCHUNK) {
        int i = b * 256 + tid;
        if (i < NN) g_rowptr[i] = g_lexcl[i] + soff[b];
        if (b == 0 && tid == 0) g_rowptr[NN] = EE;
    } else {
        int i = (b - NCHUNK) * 256 + tid;
        if (i < EE) {
            int d = dst[i];
            g_col[g_lexcl[d] + soff[d >> 8] + g_loc[i]] = src[i];
        }
    }
}

// ---------------------------------------------------------------- tensor-core GEMM0
__device__ __forceinline__ void mma16816(float* d, uint32_t a0, uint32_t a1,
                                         uint32_t a2, uint32_t a3, uint32_t b0,
                                         uint32_t b1) {
    asm volatile(
        "mma.sync.aligned.m16n8k16.row.col.f32.f16.f16.f32 "
        "{%0,%1,%2,%3}, {%4,%5,%6,%7}, {%8,%9}, {%0,%1,%2,%3};\n"
        : "+f"(d[0]), "+f"(d[1]), "+f"(d[2]), "+f"(d[3])
        : "r"(a0), "r"(a1), "r"(a2), "r"(a3), "r"(b0), "r"(b1));
}

// GEMM0: fp32 x, fp32 W0, fp16 out (tile 128x64, K=128)
__global__ void k_gemm0(const float* __restrict__ A, const float* __restrict__ W,
                        __half* __restrict__ C) {
    constexpr int K = DIN, LDA = K + 8, LDB = K + 8;
    extern __shared__ __half sm[];
    __half* sA = sm;
    __half* sB = sm + 128 * LDA;
    int tid = threadIdx.x;
    int base = blockIdx.x * 128;

    for (int i = tid; i < K * 64; i += 256) {
        int k = i >> 6, n = i & 63;
        sB[n * LDB + k] = __float2half_rn(W[i]);
    }
    for (int i = tid; i < 128 * (K / 4); i += 256) {
        int r = i / (K / 4), c = i % (K / 4);
        float4 v = make_float4(0.f, 0.f, 0.f, 0.f);
        if (base + r < NN) v = *(const float4*)(A + (size_t)(base + r) * K + c * 4);
        __half2* p = (__half2*)(sA + r * LDA + c * 4);
        p[0] = __floats2half2_rn(v.x, v.y);
        p[1] = __floats2half2_rn(v.z, v.w);
    }
    __syncthreads();

    int warp = tid >> 5, lane = tid & 31;
    int grp = lane >> 2, tig = lane & 3;
    int rowA = warp * 16 + grp;
    float acc[8][4];
#pragma unroll
    for (int j = 0; j < 8; j++)
#pragma unroll
        for (int q = 0; q < 4; q++) acc[j][q] = 0.f;

#pragma unroll
    for (int kc = 0; kc < K; kc += 16) {
        uint32_t a0 = *(const uint32_t*)(sA + rowA * LDA + kc + 2 * tig);
        uint32_t a1 = *(const uint32_t*)(sA + (rowA + 8) * LDA + kc + 2 * tig);
        uint32_t a2 = *(const uint32_t*)(sA + rowA * LDA + kc + 2 * tig + 8);
        uint32_t a3 = *(const uint32_t*)(sA + (rowA + 8) * LDA + kc + 2 * tig + 8);
#pragma unroll
        for (int j = 0; j < 8; j++) {
            uint32_t b0 = *(const uint32_t*)(sB + (j * 8 + grp) * LDB + kc + 2 * tig);
            uint32_t b1 = *(const uint32_t*)(sB + (j * 8 + grp) * LDB + kc + 2 * tig + 8);
            mma16816(acc[j], a0, a1, a2, a3, b0, b1);
        }
    }
    int r0 = base + rowA, r1 = r0 + 8;
#pragma unroll
    for (int j = 0; j < 8; j++) {
        int col = j * 8 + 2 * tig;
        if (r0 < NN)
            *(__half2*)(C + (size_t)r0 * DH + col) = __floats2half2_rn(acc[j][0], acc[j][1]);
        if (r1 < NN)
            *(__half2*)(C + (size_t)r1 * DH + col) = __floats2half2_rn(acc[j][2], acc[j][3]);
    }
}

// ------------------------------------------------------- aggregation body
__device__ __forceinline__ float2 agg_node(const __half2* __restrict__ hin, int node,
                                           int lane, float2 bb) {
    float dd = g_dinv[node];
    int beg = g_rowptr[node], end = g_rowptr[node + 1];
    float2 hv = __half22float2(hin[(size_t)node * 32 + lane]);
    float2 acc = make_float2(hv.x * dd * dd, hv.y * dd * dd);
    int k = beg;
    for (; k + 4 <= end; k += 4) {
        int j0 = g_col[k], j1 = g_col[k + 1], j2 = g_col[k + 2], j3 = g_col[k + 3];
        float n0 = g_dinv[j0] * dd, n1 = g_dinv[j1] * dd;
        float n2 = g_dinv[j2] * dd, n3 = g_dinv[j3] * dd;
        float2 h0 = __half22float2(hin[(size_t)j0 * 32 + lane]);
        float2 h1 = __half22float2(hin[(size_t)j1 * 32 + lane]);
        float2 h2 = __half22float2(hin[(size_t)j2 * 32 + lane]);
        float2 h3 = __half22float2(hin[(size_t)j3 * 32 + lane]);
        acc.x = fmaf(h0.x, n0, acc.x); acc.y = fmaf(h0.y, n0, acc.y);
        acc.x = fmaf(h1.x, n1, acc.x); acc.y = fmaf(h1.y, n1, acc.y);
        acc.x = fmaf(h2.x, n2, acc.x); acc.y = fmaf(h2.y, n2, acc.y);
        acc.x = fmaf(h3.x, n3, acc.x); acc.y = fmaf(h3.y, n3, acc.y);
    }
    for (; k < end; k++) {
        int j = g_col[k];
        float n = g_dinv[j] * dd;
        float2 h = __half22float2(hin[(size_t)j * 32 + lane]);
        acc.x = fmaf(h.x, n, acc.x);
        acc.y = fmaf(h.y, n, acc.y);
    }
    acc.x += bb.x;
    acc.y += bb.y;
    acc.x = (acc.x > 0.f) ? acc.x : expm1f(acc.x);
    acc.y = (acc.y > 0.f) ? acc.y : expm1f(acc.y);
    return acc;
}

// ------------------------------------------------------- agg + ELU + next-layer matmul fused
// warp per node; W (64x64 fp32) preloaded in smem; out fp16 = ELU(agg)+b then @W
__global__ void k_agg_mm(const __half2* __restrict__ hin, __half2* __restrict__ hout,
                         const float* __restrict__ bias, const float* __restrict__ W) {
    __shared__ float sW[DH * DH];    // 16 KB, W[k*64+n]
    __shared__ float sh[8][DH];
    for (int i = threadIdx.x; i < DH * DH / 4; i += 256)
        *(float4*)(sW + i * 4) = *(const float4*)(W + i * 4);
    __syncthreads();
    int warp = threadIdx.x >> 5, lane = threadIdx.x & 31;
    int node = blockIdx.x * 8 + warp;
    if (node >= NN) return;
    float2 bb = ((const float2*)bias)[lane];
    float2 a = agg_node(hin, node, lane, bb);
    sh[warp][2 * lane] = a.x;
    sh[warp][2 * lane + 1] = a.y;
    __syncwarp();
    float2 v = make_float2(0.f, 0.f);
#pragma unroll
    for (int k = 0; k < DH; k++) {
        float hk = sh[warp][k];
        float2 w = *(const float2*)(sW + k * DH + 2 * lane);
        v.x = fmaf(hk, w.x, v.x);
        v.y = fmaf(hk, w.y, v.y);
    }
    hout[(size_t)node * 32 + lane] = __floats2half2_rn(v.x, v.y);
}

// last aggregation + FC + softmax fused
__global__ void k_agg_fc(const __half2* __restrict__ hin, const float* __restrict__ bias,
                         const float* __restrict__ fw, const float* __restrict__ fb,
                         float* __restrict__ out) {
    __shared__ float sW[DH * DOUT];
    __shared__ float sh[8][DH];
    for (int i = threadIdx.x; i < DH * DOUT; i += 256) sW[i] = fw[i];
    __syncthreads();
    int warp = threadIdx.x >> 5, lane = threadIdx.x & 31;
    int node = blockIdx.x * 8 + warp;
    if (node >= NN) return;
    float2 bb = ((const float2*)bias)[lane];
    float2 acc = agg_node(hin, node, lane, bb);
    sh[warp][2 * lane] = acc.x;
    sh[warp][2 * lane + 1] = acc.y;
    __syncwarp();
    float v = 0.f;
    if (lane < DOUT) {
        v = fb[lane];
#pragma unroll
        for (int kk = 0; kk < DH; kk++) v = fmaf(sh[warp][kk], sW[kk * DOUT + lane], v);
    }
    float m = v;
#pragma unroll
    for (int o = 8; o; o >>= 1) m = fmaxf(m, __shfl_xor_sync(0xffffffffu, m, o, 16));
    float e = (lane < DOUT) ? expf(v - m) : 0.f;
    float s = e;
#pragma unroll
    for (int o = 8; o; o >>= 1) s += __shfl_xor_sync(0xffffffffu, s, o, 16);
    if (lane < DOUT) out[(size_t)node * DOUT + lane] = e / s;
}

// ---------------------------------------------------------------- launch
extern "C" void kernel_launch(void* const* d_in, const int* in_sizes, int n_in,
                              void* d_out, int out_size) {
    const float* x = (const float*)d_in[0];
    const int* ei = (const int*)d_in[1];
    const float* w0 = (const float*)d_in[2];
    const float* b0 = (const float*)d_in[3];
    const float* w1 = (const float*)d_in[4];
    const float* b1 = (const float*)d_in[5];
    const float* w2 = (const float*)d_in[6];
    const float* b2 = (const float*)d_in[7];
    const float* fw = (const float*)d_in[8];
    const float* fb = (const float*)d_in[9];
    float* out = (float*)d_out;
    const int* src = ei;
    const int* dst = ei + EE;

    __half *p_t, *p_ha;
    int* p_cnt;
    cudaGetSymbolAddress((void**)&p_t, g_th);
    cudaGetSymbolAddress((void**)&p_ha, g_ha);
    cudaGetSymbolAddress((void**)&p_cnt, g_cnt);

    const int smem128 = (128 * (DIN + 8) + 64 * (DIN + 8)) * 2;  // 52224 B

    static cudaStream_t s2 = nullptr;
    static cudaEvent_t evFork = nullptr, evJoin = nullptr;
    if (!s2) {
        cudaStreamCreateWithFlags(&s2, cudaStreamNonBlocking);
        cudaEventCreateWithFlags(&evFork, cudaEventDisableTiming);
        cudaEventCreateWithFlags(&evJoin, cudaEventDisableTiming);
        cudaFuncSetAttribute(k_gemm0, cudaFuncAttributeMaxDynamicSharedMemorySize, smem128);
    }

    const int gemm_grid = (NN + 127) / 128;
    const int agg_grid = (NN + 7) / 8;

    // fork: edge-preprocessing chain on s2, GEMM0 on main stream
    cudaEventRecord(evFork, 0);
    cudaStreamWaitEvent(s2, evFork, 0);
    cudaMemsetAsync(p_cnt, 0, NN * sizeof(int), s2);
    k_count<<<EBLK, 256, 0, s2>>>(dst);
    k_scan1<<<NCHUNK, 256, 0, s2>>>();
    k_finish<<<NCHUNK + EBLK, 256, 0, s2>>>(src, dst);
    cudaEventRecord(evJoin, s2);

    k_gemm0<<<gemm_grid, 256, smem128>>>(x, w0, p_t);

    cudaStreamWaitEvent(0, evJoin, 0);

    // layer0 agg + W1 matmul;  layer1 agg + W2 matmul;  layer2 agg + FC + softmax
    k_agg_mm<<<agg_grid, 256>>>((const __half2*)p_t, (__half2*)p_ha, b0, w1);
    k_agg_mm<<<agg_grid, 256>>>((const __half2*)p_ha, (__half2*)p_t, b1, w2);
    k_agg_fc<<<agg_grid, 256>>>((const __half2*)p_t, b2, fw, fb, out);
}

// round 9
// speedup vs baseline: 1.2548x; 1.2548x over previous
#include <cuda_runtime.h>
#include <cuda_fp16.h>
#include <math.h>
#include <stdint.h>

#define NN 50000
#define EE 800000
#define DIN 128
#define DH 64
#define DOUT 16
#define NCHUNK ((NN + 255) / 256)   // 196
#define EBLK ((EE + 255) / 256)     // 3125

// Scratch (device globals; no allocation allowed)
__device__ __align__(256) __half g_th[NN * DH];      // ping
__device__ __align__(256) __half g_ha[NN * DH];      // pong
__device__ float g_dinv[NN];
__device__ int g_cnt[NN];
__device__ int g_lexcl[NN];
__device__ int g_rowptr[NN + 1];
__device__ int g_loc[EE];
__device__ int g_col[EE];
__device__ int g_chtot[256];

// ---------------------------------------------------------------- preprocessing
__global__ void k_count(const int* __restrict__ dst) {
    int i = blockIdx.x * blockDim.x + threadIdx.x;
    if (i < EE) g_loc[i] = atomicAdd(&g_cnt[dst[i]], 1);
}

__global__ void k_scan1() {
    __shared__ int wsum[8];
    int tid = threadIdx.x;
    int i = blockIdx.x * 256 + tid;
    int v = (i < NN) ? g_cnt[i] : 0;
    if (i < NN) g_dinv[i] = rsqrtf((float)(v + 1));
    int lane = tid & 31, w = tid >> 5;
    int incl = v;
#pragma unroll
    for (int o = 1; o < 32; o <<= 1) {
        int t = __shfl_up_sync(0xffffffffu, incl, o);
        if (lane >= o) incl += t;
    }
    if (lane == 31) wsum[w] = incl;
    __syncthreads();
    if (w == 0) {
        int s = (lane < 8) ? wsum[lane] : 0;
#pragma unroll
        for (int o = 1; o < 8; o <<= 1) {
            int t = __shfl_up_sync(0xffffffffu, s, o);
            if (lane >= o) s += t;
        }
        if (lane < 8) wsum[lane] = s;
    }
    __syncthreads();
    int woff = (w > 0) ? wsum[w - 1] : 0;
    if (i < NN) g_lexcl[i] = woff + incl - v;
    if (tid == 255) g_chtot[blockIdx.x] = woff + incl;
}

__global__ void k_finish(const int* __restrict__ src, const int* __restrict__ dst) {
    __shared__ int soff[256];
    __shared__ int wsum[8];
    int tid = threadIdx.x;
    {
        int v = (tid < NCHUNK) ? g_chtot[tid] : 0;
        int lane = tid & 31, w = tid >> 5;
        int incl = v;
#pragma unroll
        for (int o = 1; o < 32; o <<= 1) {
            int t = __shfl_up_sync(0xffffffffu, incl, o);
            if (lane >= o) incl += t;
        }
        if (lane == 31) wsum[w] = incl;
        __syncthreads();
        if (w == 0) {
            int s = (lane < 8) ? wsum[lane] : 0;
#pragma unroll
            for (int o = 1; o < 8; o <<= 1) {
                int t = __shfl_up_sync(0xffffffffu, s, o);
                if (lane >= o) s += t;
            }
            if (lane < 8) wsum[lane] = s;
        }
        __syncthreads();
        int woff = (w > 0) ? wsum[w - 1] : 0;
        soff[tid] = woff + incl - v;
        __syncthreads();
    }
    int b = blockIdx.x;
    if (b < NCHUNK) {
        int i = b * 256 + tid;
        if (i < NN) g_rowptr[i] = g_lexcl[i] + soff[b];
        if (b == 0 && tid == 0) g_rowptr[NN] = EE;
    } else {
        int i = (b - NCHUNK) * 256 + tid;
        if (i < EE) {
            int d = dst[i];
            g_col[g_lexcl[d] + soff[d >> 8] + g_loc[i]] = src[i];
        }
    }
}

// ---------------------------------------------------------------- tensor-core GEMM
__device__ __forceinline__ void mma16816(float* d, uint32_t a0, uint32_t a1,
                                         uint32_t a2, uint32_t a3, uint32_t b0,
                                         uint32_t b1) {
    asm volatile(
        "mma.sync.aligned.m16n8k16.row.col.f32.f16.f16.f32 "
        "{%0,%1,%2,%3}, {%4,%5,%6,%7}, {%8,%9}, {%0,%1,%2,%3};\n"
        : "+f"(d[0]), "+f"(d[1]), "+f"(d[2]), "+f"(d[3])
        : "r"(a0), "r"(a1), "r"(a2), "r"(a3), "r"(b0), "r"(b1));
}

template <int K, int LDA, int LDB>
__device__ __forceinline__ void gemm_tile_compute(const __half* sA, const __half* sB,
                                                  __half* C, int base) {
    int tid = threadIdx.x;
    int warp = tid >> 5, lane = tid & 31;
    int grp = lane >> 2, tig = lane & 3;
    int rowA = warp * 16 + grp;
    float acc[8][4];
#pragma unroll
    for (int j = 0; j < 8; j++)
#pragma unroll
        for (int q = 0; q < 4; q++) acc[j][q] = 0.f;

#pragma unroll
    for (int kc = 0; kc < K; kc += 16) {
        uint32_t a0 = *(const uint32_t*)(sA + rowA * LDA + kc + 2 * tig);
        uint32_t a1 = *(const uint32_t*)(sA + (rowA + 8) * LDA + kc + 2 * tig);
        uint32_t a2 = *(const uint32_t*)(sA + rowA * LDA + kc + 2 * tig + 8);
        uint32_t a3 = *(const uint32_t*)(sA + (rowA + 8) * LDA + kc + 2 * tig + 8);
#pragma unroll
        for (int j = 0; j < 8; j++) {
            uint32_t b0 = *(const uint32_t*)(sB + (j * 8 + grp) * LDB + kc + 2 * tig);
            uint32_t b1 = *(const uint32_t*)(sB + (j * 8 + grp) * LDB + kc + 2 * tig + 8);
            mma16816(acc[j], a0, a1, a2, a3, b0, b1);
        }
    }
    int r0 = base + rowA, r1 = r0 + 8;
#pragma unroll
    for (int j = 0; j < 8; j++) {
        int col = j * 8 + 2 * tig;
        if (r0 < NN)
            *(__half2*)(C + (size_t)r0 * DH + col) = __floats2half2_rn(acc[j][0], acc[j][1]);
        if (r1 < NN)
            *(__half2*)(C + (size_t)r1 * DH + col) = __floats2half2_rn(acc[j][2], acc[j][3]);
    }
}

// GEMM0: fp32 x and fp32 W0, converted during smem stage
__global__ void k_gemm0(const float* __restrict__ A, const float* __restrict__ W,
                        __half* __restrict__ C) {
    constexpr int K = DIN, LDA = K + 8, LDB = K + 8;
    extern __shared__ __half sm[];
    __half* sA = sm;
    __half* sB = sm + 128 * LDA;
    int tid = threadIdx.x;
    int base = blockIdx.x * 128;

    for (int i = tid; i < K * 64; i += 256) {
        int k = i >> 6, n = i & 63;
        sB[n * LDB + k] = __float2half_rn(W[i]);
    }
    for (int i = tid; i < 128 * (K / 4); i += 256) {
        int r = i / (K / 4), c = i % (K / 4);
        float4 v = make_float4(0.f, 0.f, 0.f, 0.f);
        if (base + r < NN) v = *(const float4*)(A + (size_t)(base + r) * K + c * 4);
        __half2* p = (__half2*)(sA + r * LDA + c * 4);
        p[0] = __floats2half2_rn(v.x, v.y);
        p[1] = __floats2half2_rn(v.z, v.w);
    }
    __syncthreads();
    gemm_tile_compute<K, LDA, LDB>(sA, sB, C, base);
}

// GEMM 1/2: fp16 A, fp32 W converted during smem stage
__global__ void k_gemm64(const __half* __restrict__ A, const float* __restrict__ W,
                         __half* __restrict__ C) {
    constexpr int K = DH, LDA = K + 8, LDB = K + 8;
    extern __shared__ __half sm[];
    __half* sA = sm;
    __half* sB = sm + 128 * LDA;
    int tid = threadIdx.x;
    int base = blockIdx.x * 128;

    for (int i = tid; i < K * 64; i += 256) {
        int k = i >> 6, n = i & 63;
        sB[n * LDB + k] = __float2half_rn(W[i]);
    }
    for (int i = tid; i < 128 * (K / 8); i += 256) {
        int r = i / (K / 8), c = i % (K / 8);
        uint4 v = make_uint4(0u, 0u, 0u, 0u);
        if (base + r < NN) v = *(const uint4*)(A + (size_t)(base + r) * K + c * 8);
        *(uint4*)(sA + r * LDA + c * 8) = v;
    }
    __syncthreads();
    gemm_tile_compute<K, LDA, LDB>(sA, sB, C, base);
}

// ------------------------------------------------------- aggregation body (8-deep MLP)
__device__ __forceinline__ float2 agg_node(const __half2* __restrict__ hin, int node,
                                           int lane, float2 bb) {
    float dd = g_dinv[node];
    int beg = g_rowptr[node], end = g_rowptr[node + 1];
    float2 hv = __half22float2(hin[(size_t)node * 32 + lane]);
    float2 acc = make_float2(hv.x * dd * dd, hv.y * dd * dd);
    int k = beg;
    for (; k + 8 <= end; k += 8) {
        int j0 = g_col[k],     j1 = g_col[k + 1], j2 = g_col[k + 2], j3 = g_col[k + 3];
        int j4 = g_col[k + 4], j5 = g_col[k + 5], j6 = g_col[k + 6], j7 = g_col[k + 7];
        float n0 = g_dinv[j0] * dd, n1 = g_dinv[j1] * dd;
        float n2 = g_dinv[j2] * dd, n3 = g_dinv[j3] * dd;
        float n4 = g_dinv[j4] * dd, n5 = g_dinv[j5] * dd;
        float n6 = g_dinv[j6] * dd, n7 = g_dinv[j7] * dd;
        float2 h0 = __half22float2(hin[(size_t)j0 * 32 + lane]);
        float2 h1 = __half22float2(hin[(size_t)j1 * 32 + lane]);
        float2 h2 = __half22float2(hin[(size_t)j2 * 32 + lane]);
        float2 h3 = __half22float2(hin[(size_t)j3 * 32 + lane]);
        float2 h4 = __half22float2(hin[(size_t)j4 * 32 + lane]);
        float2 h5 = __half22float2(hin[(size_t)j5 * 32 + lane]);
        float2 h6 = __half22float2(hin[(size_t)j6 * 32 + lane]);
        float2 h7 = __half22float2(hin[(size_t)j7 * 32 + lane]);
        acc.x = fmaf(h0.x, n0, acc.x); acc.y = fmaf(h0.y, n0, acc.y);
        acc.x = fmaf(h1.x, n1, acc.x); acc.y = fmaf(h1.y, n1, acc.y);
        acc.x = fmaf(h2.x, n2, acc.x); acc.y = fmaf(h2.y, n2, acc.y);
        acc.x = fmaf(h3.x, n3, acc.x); acc.y = fmaf(h3.y, n3, acc.y);
        acc.x = fmaf(h4.x, n4, acc.x); acc.y = fmaf(h4.y, n4, acc.y);
        acc.x = fmaf(h5.x, n5, acc.x); acc.y = fmaf(h5.y, n5, acc.y);
        acc.x = fmaf(h6.x, n6, acc.x); acc.y = fmaf(h6.y, n6, acc.y);
        acc.x = fmaf(h7.x, n7, acc.x); acc.y = fmaf(h7.y, n7, acc.y);
    }
    for (; k + 2 <= end; k += 2) {
        int j0 = g_col[k], j1 = g_col[k + 1];
        float n0 = g_dinv[j0] * dd, n1 = g_dinv[j1] * dd;
        float2 h0 = __half22float2(hin[(size_t)j0 * 32 + lane]);
        float2 h1 = __half22float2(hin[(size_t)j1 * 32 + lane]);
        acc.x = fmaf(h0.x, n0, acc.x); acc.y = fmaf(h0.y, n0, acc.y);
        acc.x = fmaf(h1.x, n1, acc.x); acc.y = fmaf(h1.y, n1, acc.y);
    }
    if (k < end) {
        int j = g_col[k];
        float n = g_dinv[j] * dd;
        float2 h = __half22float2(hin[(size_t)j * 32 + lane]);
        acc.x = fmaf(h.x, n, acc.x);
        acc.y = fmaf(h.y, n, acc.y);
    }
    acc.x += bb.x;
    acc.y += bb.y;
    acc.x = (acc.x > 0.f) ? acc.x : expm1f(acc.x);
    acc.y = (acc.y > 0.f) ? acc.y : expm1f(acc.y);
    return acc;
}

__global__ void k_agg(const __half2* __restrict__ hin, __half2* __restrict__ hout,
                      const float* __restrict__ bias) {
    int lane = threadIdx.x;
    int node = blockIdx.x * 8 + threadIdx.y;
    if (node >= NN) return;
    float2 bb = ((const float2*)bias)[lane];
    float2 acc = agg_node(hin, node, lane, bb);
    hout[(size_t)node * 32 + lane] = __floats2half2_rn(acc.x, acc.y);
}

// last aggregation + FC + softmax fused
__global__ void k_agg_fc(const __half2* __restrict__ hin, const float* __restrict__ bias,
                         const float* __restrict__ fw, const float* __restrict__ fb,
                         float* __restrict__ out) {
    __shared__ float sW[DH * DOUT];
    __shared__ float sh[8][DH];
    for (int i = threadIdx.x; i < DH * DOUT; i += 256) sW[i] = fw[i];
    __syncthreads();
    int warp = threadIdx.x >> 5, lane = threadIdx.x & 31;
    int node = blockIdx.x * 8 + warp;
    if (node >= NN) return;
    float2 bb = ((const float2*)bias)[lane];
    float2 acc = agg_node(hin, node, lane, bb);
    sh[warp][2 * lane] = acc.x;
    sh[warp][2 * lane + 1] = acc.y;
    __syncwarp();
    float v = 0.f;
    if (lane < DOUT) {
        v = fb[lane];
#pragma unroll
        for (int kk = 0; kk < DH; kk++) v = fmaf(sh[warp][kk], sW[kk * DOUT + lane], v);
    }
    float m = v;
#pragma unroll
    for (int o = 8; o; o >>= 1) m = fmaxf(m, __shfl_xor_sync(0xffffffffu, m, o, 16));
    float e = (lane < DOUT) ? expf(v - m) : 0.f;
    float s = e;
#pragma unroll
    for (int o = 8; o; o >>= 1) s += __shfl_xor_sync(0xffffffffu, s, o, 16);
    if (lane < DOUT) out[(size_t)node * DOUT + lane] = e / s;
}

// ---------------------------------------------------------------- launch
extern "C" void kernel_launch(void* const* d_in, const int* in_sizes, int n_in,
                              void* d_out, int out_size) {
    const float* x = (const float*)d_in[0];
    const int* ei = (const int*)d_in[1];
    const float* w0 = (const float*)d_in[2];
    const float* b0 = (const float*)d_in[3];
    const float* w1 = (const float*)d_in[4];
    const float* b1 = (const float*)d_in[5];
    const float* w2 = (const float*)d_in[6];
    const float* b2 = (const float*)d_in[7];
    const float* fw = (const float*)d_in[8];
    const float* fb = (const float*)d_in[9];
    float* out = (float*)d_out;
    const int* src = ei;
    const int* dst = ei + EE;

    __half *p_t, *p_ha;
    int* p_cnt;
    cudaGetSymbolAddress((void**)&p_t, g_th);
    cudaGetSymbolAddress((void**)&p_ha, g_ha);
    cudaGetSymbolAddress((void**)&p_cnt, g_cnt);

    const int smem128 = (128 * (DIN + 8) + 64 * (DIN + 8)) * 2;  // 52224 B
    const int smem64 = (128 * (DH + 8) + 64 * (DH + 8)) * 2;     // 27648 B

    static cudaStream_t s2 = nullptr;
    static cudaEvent_t evFork = nullptr, evJoin = nullptr;
    if (!s2) {
        cudaStreamCreateWithFlags(&s2, cudaStreamNonBlocking);
        cudaEventCreateWithFlags(&evFork, cudaEventDisableTiming);
        cudaEventCreateWithFlags(&evJoin, cudaEventDisableTiming);
        cudaFuncSetAttribute(k_gemm0, cudaFuncAttributeMaxDynamicSharedMemorySize, smem128);
        cudaFuncSetAttribute(k_gemm64, cudaFuncAttributeMaxDynamicSharedMemorySize, smem64);
    }

    const int gemm_grid = (NN + 127) / 128;
    const dim3 agg_block(32, 8);
    const int agg_grid = (NN + 7) / 8;

    // fork: edge-preprocessing chain on s2, GEMM0 on main stream
    cudaEventRecord(evFork, 0);
    cudaStreamWaitEvent(s2, evFork, 0);
    cudaMemsetAsync(p_cnt, 0, NN * sizeof(int), s2);
    k_count<<<EBLK, 256, 0, s2>>>(dst);
    k_scan1<<<NCHUNK, 256, 0, s2>>>();
    k_finish<<<NCHUNK + EBLK, 256, 0, s2>>>(src, dst);
    cudaEventRecord(evJoin, s2);

    k_gemm0<<<gemm_grid, 256, smem128>>>(x, w0, p_t);

    cudaStreamWaitEvent(0, evJoin, 0);

    k_agg<<<agg_grid, agg_block>>>((const __half2*)p_t, (__half2*)p_ha, b0);
    k_gemm64<<<gemm_grid, 256, smem64>>>(p_ha, w1, p_t);
    k_agg<<<agg_grid, agg_block>>>((const __half2*)p_t, (__half2*)p_ha, b1);
    k_gemm64<<<gemm_grid, 256, smem64>>>(p_ha, w2, p_t);
    k_agg_fc<<<agg_grid, 256>>>((const __half2*)p_t, b2, fw, fb, out);
}